// round 8
// baseline (speedup 1.0000x reference)
#include <cuda_runtime.h>

#define BATCH 8
#define SEQ   1024
#define EMB   512
#define HEADS 8
#define DK    64
#define NW    8
#define BH    (BATCH*HEADS)
#define TM    128          // rows per CTA (4 warps x m=32)
#define TJ    64           // j-tile
#define VSTR  72           // V smem row stride (floats): bank=(8*tig+g+8*nb)%32 -> conflict-free

typedef unsigned long long u64;

// Precomputed tables (device globals; allocation is forbidden)
__device__ float2 g_cs[BH*NW*SEQ];          // (cos, sin) per (bh, wire, s)
__device__ float  g_vh[(size_t)BH*SEQ*DK];  // V rounded to tf32 (fp32 bit layout)

// ---- packed f32x2 helpers ----
static __device__ __forceinline__ u64 f2_pack(float x, float y){
    u64 r; asm("mov.b64 %0, {%1, %2};" : "=l"(r) : "f"(x), "f"(y)); return r;
}
static __device__ __forceinline__ float2 f2_unpack(u64 v){
    float2 r; asm("mov.b64 {%0, %1}, %2;" : "=f"(r.x), "=f"(r.y) : "l"(v)); return r;
}
static __device__ __forceinline__ u64 f2_fma(u64 a, u64 b, u64 c){
    u64 d; asm("fma.rn.f32x2 %0, %1, %2, %3;" : "=l"(d) : "l"(a), "l"(b), "l"(c)); return d;
}
static __device__ __forceinline__ u64 f2_mul(u64 a, u64 b){
    u64 d; asm("mul.rn.f32x2 %0, %1, %2;" : "=l"(d) : "l"(a), "l"(b)); return d;
}
static __device__ __forceinline__ unsigned cvt_tf32(float f){
    unsigned r; asm("cvt.rna.tf32.f32 %0, %1;" : "=r"(r) : "f"(f)); return r;
}

// Pass 1a: cos/sin table. One thread per (bh, w, s): 512K threads.
__global__ void precompute_cs(const float* __restrict__ x){
    int idx = blockIdx.x*blockDim.x + threadIdx.x;      // (bh*NW + w)*SEQ + s
    int s   = idx & (SEQ-1);
    int bhw = idx >> 10;
    int w   = bhw & (NW-1);
    int bh  = bhw >> 3;
    int b = bh >> 3, h = bh & 7;
    float v = x[((size_t)(b*SEQ + s))*EMB + h*DK + w];
    float sn, cs;
    sincosf(0.5f*v, &sn, &cs);
    g_cs[idx] = make_float2(cs, sn);
}

// Pass 1b: tf32-rounded V. One thread per float4: 1M threads.
__global__ void precompute_vh(const float* __restrict__ x){
    int idx = blockIdx.x*blockDim.x + threadIdx.x;      // (bh*SEQ+s)*16 + d4
    int d4  = idx & 15;
    int bhs = idx >> 4;
    int s   = bhs & (SEQ-1);
    int bh  = bhs >> 10;
    int b = bh >> 3, h = bh & 7;
    float4 v = ((const float4*)x)[((size_t)(b*SEQ + s))*(EMB/4) + h*(DK/4) + d4];
    float4 o;
    o.x = __uint_as_float(cvt_tf32(v.x));
    o.y = __uint_as_float(cvt_tf32(v.y));
    o.z = __uint_as_float(cvt_tf32(v.z));
    o.w = __uint_as_float(cvt_tf32(v.w));
    ((float4*)g_vh)[idx] = o;
}

// Pass 2: fused score (f32x2 over row-pairs) -> exp -> tensor-core PV (tf32 hi)
// -> normalize. 4 warps; warp w owns rows [w*32, w*32+32) as TWO m16 MMA blocks
// sharing B fragments. Thread (g,tig): rows {g, g+8, g+16, g+24},
// cols j = 8*kb + {tig, tig+4}.
__global__ void __launch_bounds__(128, 3)
qk_attn5(float* __restrict__ out){
    __shared__ __align__(16) float2 sCC[NW][TJ];   // (cos, cos) duplicated
    __shared__ __align__(16) float2 sSS[NW][TJ];   // (sin, sin) duplicated
    __shared__ __align__(16) float  sVh[TJ*VSTR];

    const int bh = blockIdx.y, b = bh >> 3, h = bh & 7;
    const int tid = threadIdx.x;
    const int w   = tid >> 5;
    const int lane = tid & 31;
    const int g   = lane >> 2, tig = lane & 3;
    const int ibase = blockIdx.x*TM + w*32 + g;   // row r -> ibase + 8r

    // i-side wire values packed over row-pairs: pair0=(g, g+8), pair1=(g+16, g+24)
    u64 cip[2][NW], sip[2][NW];
#pragma unroll
    for (int p = 0; p < 2; ++p)
#pragma unroll
        for (int q = 0; q < NW; ++q){
            float2 a = g_cs[(bh*NW + q)*SEQ + ibase + 16*p];
            float2 c = g_cs[(bh*NW + q)*SEQ + ibase + 16*p + 8];
            cip[p][q] = f2_pack(a.x, c.x);
            sip[p][q] = f2_pack(a.y, c.y);
        }

    float acc0[8][4], acc1[8][4];   // block0: rows g,g+8; block1: rows g+16,g+24
#pragma unroll
    for (int nb = 0; nb < 8; ++nb)
#pragma unroll
        for (int k = 0; k < 4; ++k){ acc0[nb][k] = 0.f; acc1[nb][k] = 0.f; }
    float ps[4] = {0.f, 0.f, 0.f, 0.f};

    for (int jt = 0; jt < SEQ/TJ; ++jt){
        const int j0 = jt*TJ;
        // stage score tiles: 512 (wire,j) entries -> 4 per thread, duplicated lanes
#pragma unroll
        for (int r = 0; r < 4; ++r){
            int e = tid + r*128;
            int wi = e >> 6, jj = e & 63;
            float2 cs = g_cs[(bh*NW + wi)*SEQ + j0 + jj];
            sCC[wi][jj] = make_float2(cs.x, cs.x);
            sSS[wi][jj] = make_float2(cs.y, cs.y);
        }
        // stage V tile: 64 rows x 16 float4 = 1024 float4 -> 8 per thread
#pragma unroll
        for (int r = 0; r < 8; ++r){
            int l = tid + r*128;
            int row = l >> 4, c4 = l & 15;
            *(float4*)&sVh[row*VSTR + c4*4] =
                ((const float4*)g_vh)[((size_t)bh*SEQ + j0 + row)*(DK/4) + c4];
        }
        __syncthreads();

#pragma unroll
        for (int kb = 0; kb < 8; ++kb){
            const int ja = kb*8 + tig, jb = ja + 4;
            // 4 packed chains: {pair0,pair1} x {ja,jb}
            u64 pa0, pa1, pb0, pb1;
            {
                u64 ca = *(const u64*)&sCC[0][ja], sa = *(const u64*)&sSS[0][ja];
                u64 cb = *(const u64*)&sCC[0][jb], sb = *(const u64*)&sSS[0][jb];
                pa0 = f2_fma(sip[0][0], sa, f2_mul(cip[0][0], ca));
                pa1 = f2_fma(sip[1][0], sa, f2_mul(cip[1][0], ca));
                pb0 = f2_fma(sip[0][0], sb, f2_mul(cip[0][0], cb));
                pb1 = f2_fma(sip[1][0], sb, f2_mul(cip[1][0], cb));
            }
#pragma unroll
            for (int q = 1; q < NW; ++q){
                u64 ca = *(const u64*)&sCC[q][ja], sa = *(const u64*)&sSS[q][ja];
                u64 cb = *(const u64*)&sCC[q][jb], sb = *(const u64*)&sSS[q][jb];
                pa0 = f2_mul(pa0, f2_fma(sip[0][q], sa, f2_mul(cip[0][q], ca)));
                pa1 = f2_mul(pa1, f2_fma(sip[1][q], sa, f2_mul(cip[1][q], ca)));
                pb0 = f2_mul(pb0, f2_fma(sip[0][q], sb, f2_mul(cip[0][q], cb)));
                pb1 = f2_mul(pb1, f2_fma(sip[1][q], sb, f2_mul(cip[1][q], cb)));
            }
            float2 A0 = f2_unpack(pa0), A1 = f2_unpack(pa1);
            float2 B0 = f2_unpack(pb0), B1 = f2_unpack(pb1);
            // diagonal score = 1 is the softmax max -> raw exp is safe
            float eA0 = __expf(fabsf(A0.x));   // p(g,     ja)
            float eA1 = __expf(fabsf(A0.y));   // p(g+8,   ja)
            float eA2 = __expf(fabsf(A1.x));   // p(g+16,  ja)
            float eA3 = __expf(fabsf(A1.y));   // p(g+24,  ja)
            float eB0 = __expf(fabsf(B0.x));   // p(g,     jb)
            float eB1 = __expf(fabsf(B0.y));   // p(g+8,   jb)
            float eB2 = __expf(fabsf(B1.x));   // p(g+16,  jb)
            float eB3 = __expf(fabsf(B1.y));   // p(g+24,  jb)
            ps[0] += eA0 + eB0;
            ps[1] += eA1 + eB1;
            ps[2] += eA2 + eB2;
            ps[3] += eA3 + eB3;

            // tf32 A-fragments (hi only; V already tf32)
            unsigned a00 = cvt_tf32(eA0), a01 = cvt_tf32(eA1);
            unsigned a02 = cvt_tf32(eB0), a03 = cvt_tf32(eB1);
            unsigned a10 = cvt_tf32(eA2), a11 = cvt_tf32(eA3);
            unsigned a12 = cvt_tf32(eB2), a13 = cvt_tf32(eB3);

            const float* vA = &sVh[ja*VSTR + g];
            const float* vB = &sVh[jb*VSTR + g];
#pragma unroll
            for (int nb = 0; nb < 8; ++nb){
                unsigned b0 = __float_as_uint(vA[nb*8]);
                unsigned b1 = __float_as_uint(vB[nb*8]);
                asm volatile(
                    "mma.sync.aligned.m16n8k8.row.col.f32.tf32.tf32.f32 "
                    "{%0,%1,%2,%3}, {%4,%5,%6,%7}, {%8,%9}, {%0,%1,%2,%3};"
                    : "+f"(acc0[nb][0]), "+f"(acc0[nb][1]),
                      "+f"(acc0[nb][2]), "+f"(acc0[nb][3])
                    : "r"(a00), "r"(a01), "r"(a02), "r"(a03), "r"(b0), "r"(b1));
                asm volatile(
                    "mma.sync.aligned.m16n8k8.row.col.f32.tf32.tf32.f32 "
                    "{%0,%1,%2,%3}, {%4,%5,%6,%7}, {%8,%9}, {%0,%1,%2,%3};"
                    : "+f"(acc1[nb][0]), "+f"(acc1[nb][1]),
                      "+f"(acc1[nb][2]), "+f"(acc1[nb][3])
                    : "r"(a10), "r"(a11), "r"(a12), "r"(a13), "r"(b0), "r"(b1));
            }
        }
        __syncthreads();
    }

    // row sums: reduce over the 4 tig lanes (xor 1, 2)
#pragma unroll
    for (int r = 0; r < 4; ++r){
        ps[r] += __shfl_xor_sync(0xffffffffu, ps[r], 1);
        ps[r] += __shfl_xor_sync(0xffffffffu, ps[r], 2);
    }
    const float inv0 = 1.0f/ps[0], inv1 = 1.0f/ps[1];
    const float inv2 = 1.0f/ps[2], inv3 = 1.0f/ps[3];

#pragma unroll
    for (int nb = 0; nb < 8; ++nb){
        size_t col = h*DK + nb*8 + 2*tig;
        size_t o0 = ((size_t)(b*SEQ + ibase +  0))*EMB + col;
        size_t o1 = ((size_t)(b*SEQ + ibase +  8))*EMB + col;
        size_t o2 = ((size_t)(b*SEQ + ibase + 16))*EMB + col;
        size_t o3 = ((size_t)(b*SEQ + ibase + 24))*EMB + col;
        *(float2*)&out[o0] = make_float2(acc0[nb][0]*inv0, acc0[nb][1]*inv0);
        *(float2*)&out[o1] = make_float2(acc0[nb][2]*inv1, acc0[nb][3]*inv1);
        *(float2*)&out[o2] = make_float2(acc1[nb][0]*inv2, acc1[nb][1]*inv2);
        *(float2*)&out[o3] = make_float2(acc1[nb][2]*inv3, acc1[nb][3]*inv3);
    }
}

extern "C" void kernel_launch(void* const* d_in, const int* in_sizes, int n_in,
                              void* d_out, int out_size){
    const float* x = (const float*)d_in[0];
    float* out = (float*)d_out;
    precompute_cs<<<(BH*NW*SEQ)/256, 256>>>(x);
    precompute_vh<<<((size_t)BH*SEQ*16)/256, 256>>>(x);
    dim3 grid(SEQ/TM, BH);
    qk_attn5<<<grid, 128>>>(out);
}